// round 15
// baseline (speedup 1.0000x reference)
#include <cuda_runtime.h>
#include <cstdint>

// ---------------------------------------------------------------------------
// Problem constants
// ---------------------------------------------------------------------------
#define BB 4
#define HH 224
#define WW 224
#define HW (HH * WW)                 // 50176
#define NPLANE 128                   // B*C
#define NTOT ((size_t)NPLANE * HW)   // 6,422,528 floats

// vertical scan pipeline
#define ST 4
#define NS 3
#define NGRP (HH / ST)               // 56

// horizontal scan slab pipeline
#define STH 32                       // steps per stage (128B per row per array)
#define NSH 2
#define HGRP (WW / STH)              // 7
#define HARR (224 * STH * 4)         // bytes per array per stage = 28672
#define HSTAGEB (4 * HARR)           // 114688
#define HSMEM (NSH * HSTAGEB + 2 * 226 * 4)  // 231184

// Scratch (no cudaMalloc allowed)
__device__ __align__(256) float g_x[NTOT];
__device__ __align__(256) float g_dir[4 * NTOT];  // d0,d3 transposed layout

// ---------------------------------------------------------------------------
// cp.async helpers
// ---------------------------------------------------------------------------
__device__ __forceinline__ uint32_t s2u(const void* p) {
    return (uint32_t)__cvta_generic_to_shared(p);
}
__device__ __forceinline__ void cpa16(uint32_t dst, const float* src) {
    asm volatile("cp.async.cg.shared.global [%0], [%1], 16;" ::"r"(dst),
                 "l"(src));
}
__device__ __forceinline__ void cpa16p(float* dst, const float* src) {
    cpa16(s2u(dst), src);
}
__device__ __forceinline__ void cpa_commit() {
    asm volatile("cp.async.commit_group;");
}
__device__ __forceinline__ void cpa_wait2() {
    asm volatile("cp.async.wait_group 2;");
}
__device__ __forceinline__ void cpa_wait1() {
    asm volatile("cp.async.wait_group 1;");
}

// ---------------------------------------------------------------------------
// K0: conv2d 3x3 same, 2 -> 32, writes g_x
// ---------------------------------------------------------------------------
__global__ void conv_in_kernel(const float* __restrict__ y,
                               const float* __restrict__ w3) {
    __shared__ float ws[576];
    for (int i = threadIdx.x; i < 576; i += blockDim.x) ws[i] = w3[i];
    __syncthreads();

    int idx = blockIdx.x * blockDim.x + threadIdx.x;
    if (idx >= BB * HW) return;
    int b = idx / HW, pix = idx - b * HW;
    int py = pix / WW, px = pix - py * WW;

    float in[2][3][3];
#pragma unroll
    for (int ic = 0; ic < 2; ic++)
#pragma unroll
        for (int ky = 0; ky < 3; ky++)
#pragma unroll
            for (int kx = 0; kx < 3; kx++) {
                int yy = py + ky - 1, xx = px + kx - 1;
                bool v = ((unsigned)yy < HH) && ((unsigned)xx < WW);
                in[ic][ky][kx] =
                    v ? __ldg(y + ((size_t)(b * 2 + ic)) * HW + yy * WW + xx)
                      : 0.0f;
            }

    for (int oc = 0; oc < 32; oc++) {
        float a = 0.0f;
#pragma unroll
        for (int ic = 0; ic < 2; ic++)
#pragma unroll
            for (int k = 0; k < 9; k++)
                a += in[ic][k / 3][k % 3] * ws[(oc * 2 + ic) * 9 + k];
        g_x[((size_t)(b * 32 + oc)) * HW + pix] = a;
    }
}

// ---------------------------------------------------------------------------
// Vertical scan (d1 rl = H reverse, d2 du = H forward).
// ---------------------------------------------------------------------------
template <bool REV>
__device__ void scan_v_body(const float* __restrict__ g1,
                            const float* __restrict__ g2,
                            const float* __restrict__ g3,
                            const float* __restrict__ xp,
                            float* __restrict__ yp,
                            float (*sbuf)[4][ST * 224], float (*hbuf)[226],
                            int s) {
    const float* arr[4] = {g1, g2, g3, xp};
    const int jf = s / 56, qf = s - jf * 56;

    auto fill = [&](int st, int tg) {
        int row = REV ? 223 - (4 * tg + jf) : 4 * tg + jf;
#pragma unroll
        for (int a = 0; a < 4; a++)
            cpa16p(&sbuf[st][a][jf * 224 + qf * 4],
                   arr[a] + (size_t)row * WW + qf * 4);
        cpa_commit();
    };

    fill(0, 0);
    fill(1, 1);
    fill(2, 2);

    int cur = 0;
    float hown = 0.0f;

    for (int tg = 0; tg < NGRP; tg++) {
        int st = tg % NS;
        cpa_wait2();
        __syncthreads();

        float a1[ST], a2[ST], a3[ST], cx[ST];
#pragma unroll
        for (int j = 0; j < ST; j++) {
            float G1 = sbuf[st][0][j * 224 + s];
            float G2 = sbuf[st][1][j * 224 + s];
            float G3 = sbuf[st][2][j * 224 + s];
            float X = sbuf[st][3][j * 224 + s];
            float inv = __fdividef(
                1.0f, fmaxf(fabsf(G1) + fabsf(G2) + fabsf(G3), 1.0f));
            a1[j] = G1 * inv;
            a2[j] = G2 * inv;
            a3[j] = G3 * inv;
            cx[j] = (1.0f - a1[j] - a2[j] - a3[j]) * X;
        }

#pragma unroll
        for (int j = 0; j < ST; j++) {
            float hl = hbuf[cur][s];
            float hr = hbuf[cur][s + 2];
            float hn =
                fmaf(a1[j], hl, fmaf(a2[j], hown, fmaf(a3[j], hr, cx[j])));
            hbuf[cur ^ 1][s + 1] = hn;
            hown = hn;
            cur ^= 1;
            __syncthreads();
            int row = REV ? 223 - (4 * tg + j) : 4 * tg + j;
            yp[(size_t)row * WW + s] = hn;  // coalesced
        }

        int nt = tg + NS;
        if (nt < NGRP) fill(st, nt);
        else cpa_commit();
    }
}

__global__ void __launch_bounds__(224) scan_v_kernel(
    const float* __restrict__ gates) {
    __shared__ float sbuf[NS][4][ST * 224];
    __shared__ float hbuf[2][226];

    int s = threadIdx.x;
    int plane = blockIdx.x;
    int d = blockIdx.y + 1;  // 1 or 2
    int b = plane >> 5, c = plane & 31;
    int grp0 = (d == 1) ? 3 : 6;

    const float* g1 = gates + ((size_t)(b * 384 + (grp0 + 0) * 32 + c)) * HW;
    const float* g2 = gates + ((size_t)(b * 384 + (grp0 + 1) * 32 + c)) * HW;
    const float* g3 = gates + ((size_t)(b * 384 + (grp0 + 2) * 32 + c)) * HW;
    const float* xp = g_x + (size_t)plane * HW;
    float* yp = g_dir + (size_t)d * NTOT + (size_t)plane * HW;

    hbuf[0][s + 1] = 0.0f;
    if (s < 2) { hbuf[0][s * 225] = 0.0f; hbuf[1][s * 225] = 0.0f; }
    __syncthreads();

    if (d == 1) scan_v_body<true>(g1, g2, g3, xp, yp, sbuf, hbuf, s);
    else        scan_v_body<false>(g1, g2, g3, xp, yp, sbuf, hbuf, s);
}

// ---------------------------------------------------------------------------
// Horizontal scan on NATIVE input layout (d0 lr = W fwd, d3 ud = W rev).
// Slab stage: 4 arrays x 224 rows x 32 cols; swizzle c^(row&7) keeps fill and
// stride-128B consume conflict-free. Output written TRANSPOSED (coalesced):
// yp[col*224 + row].  (R13-proven path.)
// ---------------------------------------------------------------------------
template <bool REV>
__device__ void scan_h_body(const float* __restrict__ g1,
                            const float* __restrict__ g2,
                            const float* __restrict__ g3,
                            const float* __restrict__ xp,
                            float* __restrict__ yp, char* slab,
                            float (*hbuf)[226], int s) {
    const float* arr[4] = {g1, g2, g3, xp};

    auto fill = [&](int st, int tg) {
        uint32_t sb = s2u(slab) + (uint32_t)(st * HSTAGEB);
        int base = REV ? 192 - 32 * tg : 32 * tg;
#pragma unroll
        for (int i = 0; i < 32; i++) {
            int a = i >> 3;
            int r = (i & 7) * 224 + s;
            int row = r >> 3, ch = r & 7;
            cpa16(sb + (uint32_t)(a * HARR + row * 128 +
                                  ((ch ^ (row & 7)) << 4)),
                  arr[a] + (size_t)row * WW + base + ch * 4);
        }
        cpa_commit();
    };

    fill(0, 0);
    fill(1, 1);

    int cur = 0;
    float hown = 0.0f;

    for (int tg = 0; tg < HGRP; tg++) {
        int st = tg & 1;
        cpa_wait1();
        __syncthreads();
        char* sp = slab + st * HSTAGEB;

#pragma unroll
        for (int m = 0; m < 8; m++) {
            int cm = REV ? 7 - m : m;
            float4 q[4];
#pragma unroll
            for (int a = 0; a < 4; a++)
                q[a] = *(const float4*)(sp + a * HARR + s * 128 +
                                        ((cm ^ (s & 7)) << 4));

            float a1[4], a2[4], a3[4], cx[4];
#pragma unroll
            for (int j = 0; j < 4; j++) {
                int cc = REV ? 3 - j : j;
                float G1 = ((const float*)&q[0])[cc];
                float G2 = ((const float*)&q[1])[cc];
                float G3 = ((const float*)&q[2])[cc];
                float X = ((const float*)&q[3])[cc];
                float inv = __fdividef(
                    1.0f, fmaxf(fabsf(G1) + fabsf(G2) + fabsf(G3), 1.0f));
                a1[j] = G1 * inv;
                a2[j] = G2 * inv;
                a3[j] = G3 * inv;
                cx[j] = (1.0f - a1[j] - a2[j] - a3[j]) * X;
            }

#pragma unroll
            for (int j = 0; j < 4; j++) {
                float hl = hbuf[cur][s];
                float hr = hbuf[cur][s + 2];
                float hn = fmaf(a1[j], hl,
                                fmaf(a2[j], hown, fmaf(a3[j], hr, cx[j])));
                hbuf[cur ^ 1][s + 1] = hn;
                hown = hn;
                cur ^= 1;
                __syncthreads();
                int t = 32 * tg + 4 * m + j;
                int col = REV ? 223 - t : t;
                yp[(size_t)col * 224 + s] = hn;  // transposed, coalesced
            }
        }

        if (tg + 2 < HGRP) fill(st, tg + 2);
        else cpa_commit();
    }
}

__global__ void __launch_bounds__(224) scan_h_kernel(
    const float* __restrict__ gates) {
    extern __shared__ __align__(128) char hsm[];
    float(*hbuf)[226] = (float(*)[226])(hsm + NSH * HSTAGEB);

    int s = threadIdx.x;
    int plane = blockIdx.x;
    int dh = blockIdx.y;  // 0 -> d0 (fwd), 1 -> d3 (rev)
    int b = plane >> 5, c = plane & 31;
    int grp0 = dh ? 9 : 0;

    const float* g1 = gates + ((size_t)(b * 384 + (grp0 + 0) * 32 + c)) * HW;
    const float* g2 = gates + ((size_t)(b * 384 + (grp0 + 1) * 32 + c)) * HW;
    const float* g3 = gates + ((size_t)(b * 384 + (grp0 + 2) * 32 + c)) * HW;
    const float* xp = g_x + (size_t)plane * HW;
    float* yp = g_dir + (size_t)(dh ? 3 : 0) * NTOT + (size_t)plane * HW;

    hbuf[0][s + 1] = 0.0f;
    if (s < 2) { hbuf[0][s * 225] = 0.0f; hbuf[1][s * 225] = 0.0f; }
    __syncthreads();

    if (dh) scan_h_body<true>(g1, g2, g3, xp, yp, hsm, hbuf, s);
    else    scan_h_body<false>(g1, g2, g3, xp, yp, hsm, hbuf, s);
}

// ---------------------------------------------------------------------------
// Combine (pass 1): max over 4 dirs; d0,d3 transposed. Tiled 32x32. Writes g_x.
// ---------------------------------------------------------------------------
__global__ void combine_t_kernel() {
    __shared__ float t0[32][33], t3[32][33];
    int plane = blockIdx.z;
    const float* p0t = g_dir + 0 * NTOT + (size_t)plane * HW;
    const float* p1 = g_dir + 1 * NTOT + (size_t)plane * HW;
    const float* p2 = g_dir + 2 * NTOT + (size_t)plane * HW;
    const float* p3t = g_dir + 3 * NTOT + (size_t)plane * HW;
    int x0 = blockIdx.x * 32, y0 = blockIdx.y * 32;
    int tx = threadIdx.x;

#pragma unroll
    for (int dy = threadIdx.y; dy < 32; dy += 8) {
        t0[dy][tx] = p0t[(x0 + dy) * HH + y0 + tx];
        t3[dy][tx] = p3t[(x0 + dy) * HH + y0 + tx];
    }
    __syncthreads();
#pragma unroll
    for (int dy = threadIdx.y; dy < 32; dy += 8) {
        float v1 = p1[(y0 + dy) * WW + x0 + tx];
        float v2 = p2[(y0 + dy) * WW + x0 + tx];
        float v0 = t0[tx][dy];
        float v3 = t3[tx][dy];
        g_x[(size_t)plane * HW + (y0 + dy) * WW + x0 + tx] =
            fmaxf(fmaxf(v0, v3), fmaxf(v1, v2));
    }
}

// ---------------------------------------------------------------------------
// FUSED pass-2 epilogue: combine(max of 4 dirs; d0,d3 TRANSPOSED) +
// conv2d 3x3 (32->2) + log_softmax. Grid (7,7,B); block 32x8.
// Phase A: native d1,d2 halo tile; Phase B: transposed-major traversal for
// d0,d3 (contiguous in ry); stride-35 smem RMW is conflict-free (gcd(35,32)=1).
// ---------------------------------------------------------------------------
__global__ void __launch_bounds__(256) fused_out_kernel(
    const float* __restrict__ w4, float* __restrict__ out) {
    __shared__ float ws[576];
    __shared__ float tile[34][35];

    int tid = threadIdx.y * 32 + threadIdx.x;
    for (int i = tid; i < 576; i += 256) ws[i] = w4[i];

    int b = blockIdx.z;
    int x0 = blockIdx.x * 32, y0 = blockIdx.y * 32;
    int tx = threadIdx.x, ty = threadIdx.y;

    float acc0[4] = {0.f, 0.f, 0.f, 0.f};
    float acc1[4] = {0.f, 0.f, 0.f, 0.f};

    const float* p0t = g_dir;
    const float* p1 = g_dir + NTOT;
    const float* p2 = g_dir + 2 * NTOT;
    const float* p3t = g_dir + 3 * NTOT;

    for (int c = 0; c < 32; c++) {
        size_t po = ((size_t)(b * 32 + c)) * HW;
        __syncthreads();  // prior conv reads done (and ws ready on c=0)

        // Phase A: native d1,d2 (contiguous in rx).
        for (int idx = tid; idx < 34 * 34; idx += 256) {
            int ry = idx / 34, rx = idx - ry * 34;
            int gy = y0 + ry - 1, gx = x0 + rx - 1;
            float v = 0.0f;
            if ((unsigned)gy < HH && (unsigned)gx < WW) {
                size_t o = po + (size_t)gy * WW + gx;
                v = fmaxf(__ldg(p1 + o), __ldg(p2 + o));
            }
            tile[ry][rx] = v;
        }
        __syncthreads();

        // Phase B: transposed d0,d3 (contiguous in ry).
        for (int idx = tid; idx < 34 * 34; idx += 256) {
            int rx = idx / 34, ry = idx - rx * 34;
            int gy = y0 + ry - 1, gx = x0 + rx - 1;
            if ((unsigned)gy < HH && (unsigned)gx < WW) {
                size_t o = po + (size_t)gx * HH + gy;
                float v = fmaxf(__ldg(p0t + o), __ldg(p3t + o));
                tile[ry][rx] = fmaxf(tile[ry][rx], v);
            }
        }
        __syncthreads();

#pragma unroll
        for (int k = 0; k < 4; k++) {
            int r = ty + 8 * k;
#pragma unroll
            for (int dy = 0; dy < 3; dy++)
#pragma unroll
                for (int dx = 0; dx < 3; dx++) {
                    float v = tile[r + dy][tx + dx];
                    int wi = c * 9 + dy * 3 + dx;
                    acc0[k] = fmaf(v, ws[wi], acc0[k]);
                    acc1[k] = fmaf(v, ws[288 + wi], acc1[k]);
                }
        }
    }

#pragma unroll
    for (int k = 0; k < 4; k++) {
        int r = ty + 8 * k;
        int pix = (y0 + r) * WW + x0 + tx;
        float a0 = acc0[k], a1 = acc1[k];
        float mx = fmaxf(a0, a1);
        float l = mx + logf(expf(a0 - mx) + expf(a1 - mx));
        out[(size_t)(b * 2) * HW + pix] = a0 - l;
        out[(size_t)(b * 2 + 1) * HW + pix] = a1 - l;
    }
}

// ---------------------------------------------------------------------------
// Launch: conv_in -> scan_v+scan_h -> combine_t -> scan_v+scan_h -> fused_out
// ---------------------------------------------------------------------------
extern "C" void kernel_launch(void* const* d_in, const int* in_sizes, int n_in,
                              void* d_out, int out_size) {
    const float* gates = (const float*)d_in[0];
    const float* y     = (const float*)d_in[1];
    const float* w3    = (const float*)d_in[2];
    const float* w4    = (const float*)d_in[3];
    float* out = (float*)d_out;

    cudaFuncSetAttribute(scan_h_kernel,
                         cudaFuncAttributeMaxDynamicSharedMemorySize, HSMEM);

    int pxblocks = (BB * HW + 255) / 256;
    dim3 sg(NPLANE, 2);
    dim3 tb(32, 8);
    dim3 cg(7, 7, NPLANE);
    dim3 fg(7, 7, BB);

    conv_in_kernel<<<pxblocks, 256>>>(y, w3);
    scan_v_kernel<<<sg, 224>>>(gates);
    scan_h_kernel<<<sg, 224, HSMEM>>>(gates);
    combine_t_kernel<<<cg, tb>>>();
    scan_v_kernel<<<sg, 224>>>(gates);
    scan_h_kernel<<<sg, 224, HSMEM>>>(gates);
    fused_out_kernel<<<fg, tb>>>(w4, out);
}

// round 16
// speedup vs baseline: 1.5291x; 1.5291x over previous
#include <cuda_runtime.h>
#include <cstdint>

// ---------------------------------------------------------------------------
// Problem constants
// ---------------------------------------------------------------------------
#define BB 4
#define HH 224
#define WW 224
#define HW (HH * WW)                 // 50176
#define NPLANE 128                   // B*C
#define NTOT ((size_t)NPLANE * HW)   // 6,422,528 floats

// vertical scan pipeline
#define ST 4
#define NS 3
#define NGRP (HH / ST)               // 56

// horizontal scan slab pipeline
#define STH 32                       // steps per stage (128B per row per array)
#define NSH 2
#define HGRP (WW / STH)              // 7
#define HARR (224 * STH * 4)         // bytes per array per stage = 28672
#define HSTAGEB (4 * HARR)           // 114688
#define HSMEM (NSH * HSTAGEB + 2 * 226 * 4)  // 231184

// Scratch (no cudaMalloc allowed)
__device__ __align__(256) float g_x[NTOT];
__device__ __align__(256) float g_dir[4 * NTOT];  // d0,d3 transposed layout

// ---------------------------------------------------------------------------
// cp.async helpers
// ---------------------------------------------------------------------------
__device__ __forceinline__ uint32_t s2u(const void* p) {
    return (uint32_t)__cvta_generic_to_shared(p);
}
__device__ __forceinline__ void cpa16(uint32_t dst, const float* src) {
    asm volatile("cp.async.cg.shared.global [%0], [%1], 16;" ::"r"(dst),
                 "l"(src));
}
__device__ __forceinline__ void cpa16p(float* dst, const float* src) {
    cpa16(s2u(dst), src);
}
__device__ __forceinline__ void cpa_commit() {
    asm volatile("cp.async.commit_group;");
}
__device__ __forceinline__ void cpa_wait2() {
    asm volatile("cp.async.wait_group 2;");
}
__device__ __forceinline__ void cpa_wait1() {
    asm volatile("cp.async.wait_group 1;");
}

// ---------------------------------------------------------------------------
// K0: conv2d 3x3 same, 2 -> 32, writes g_x
// ---------------------------------------------------------------------------
__global__ void conv_in_kernel(const float* __restrict__ y,
                               const float* __restrict__ w3) {
    __shared__ float ws[576];
    for (int i = threadIdx.x; i < 576; i += blockDim.x) ws[i] = w3[i];
    __syncthreads();

    int idx = blockIdx.x * blockDim.x + threadIdx.x;
    if (idx >= BB * HW) return;
    int b = idx / HW, pix = idx - b * HW;
    int py = pix / WW, px = pix - py * WW;

    float in[2][3][3];
#pragma unroll
    for (int ic = 0; ic < 2; ic++)
#pragma unroll
        for (int ky = 0; ky < 3; ky++)
#pragma unroll
            for (int kx = 0; kx < 3; kx++) {
                int yy = py + ky - 1, xx = px + kx - 1;
                bool v = ((unsigned)yy < HH) && ((unsigned)xx < WW);
                in[ic][ky][kx] =
                    v ? __ldg(y + ((size_t)(b * 2 + ic)) * HW + yy * WW + xx)
                      : 0.0f;
            }

    for (int oc = 0; oc < 32; oc++) {
        float a = 0.0f;
#pragma unroll
        for (int ic = 0; ic < 2; ic++)
#pragma unroll
            for (int k = 0; k < 9; k++)
                a += in[ic][k / 3][k % 3] * ws[(oc * 2 + ic) * 9 + k];
        g_x[((size_t)(b * 32 + oc)) * HW + pix] = a;
    }
}

// ---------------------------------------------------------------------------
// Vertical scan (d1 rl = H reverse, d2 du = H forward).
// ---------------------------------------------------------------------------
template <bool REV>
__device__ void scan_v_body(const float* __restrict__ g1,
                            const float* __restrict__ g2,
                            const float* __restrict__ g3,
                            const float* __restrict__ xp,
                            float* __restrict__ yp,
                            float (*sbuf)[4][ST * 224], float (*hbuf)[226],
                            int s) {
    const float* arr[4] = {g1, g2, g3, xp};
    const int jf = s / 56, qf = s - jf * 56;

    auto fill = [&](int st, int tg) {
        int row = REV ? 223 - (4 * tg + jf) : 4 * tg + jf;
#pragma unroll
        for (int a = 0; a < 4; a++)
            cpa16p(&sbuf[st][a][jf * 224 + qf * 4],
                   arr[a] + (size_t)row * WW + qf * 4);
        cpa_commit();
    };

    fill(0, 0);
    fill(1, 1);
    fill(2, 2);

    int cur = 0;
    float hown = 0.0f;

    for (int tg = 0; tg < NGRP; tg++) {
        int st = tg % NS;
        cpa_wait2();
        __syncthreads();

        float a1[ST], a2[ST], a3[ST], cx[ST];
#pragma unroll
        for (int j = 0; j < ST; j++) {
            float G1 = sbuf[st][0][j * 224 + s];
            float G2 = sbuf[st][1][j * 224 + s];
            float G3 = sbuf[st][2][j * 224 + s];
            float X = sbuf[st][3][j * 224 + s];
            float inv = __fdividef(
                1.0f, fmaxf(fabsf(G1) + fabsf(G2) + fabsf(G3), 1.0f));
            a1[j] = G1 * inv;
            a2[j] = G2 * inv;
            a3[j] = G3 * inv;
            cx[j] = (1.0f - a1[j] - a2[j] - a3[j]) * X;
        }

#pragma unroll
        for (int j = 0; j < ST; j++) {
            float hl = hbuf[cur][s];
            float hr = hbuf[cur][s + 2];
            float hn =
                fmaf(a1[j], hl, fmaf(a2[j], hown, fmaf(a3[j], hr, cx[j])));
            hbuf[cur ^ 1][s + 1] = hn;
            hown = hn;
            cur ^= 1;
            __syncthreads();
            int row = REV ? 223 - (4 * tg + j) : 4 * tg + j;
            yp[(size_t)row * WW + s] = hn;  // coalesced
        }

        int nt = tg + NS;
        if (nt < NGRP) fill(st, nt);
        else cpa_commit();
    }
}

__global__ void __launch_bounds__(224) scan_v_kernel(
    const float* __restrict__ gates) {
    __shared__ float sbuf[NS][4][ST * 224];
    __shared__ float hbuf[2][226];

    int s = threadIdx.x;
    int plane = blockIdx.x;
    int d = blockIdx.y + 1;  // 1 or 2
    int b = plane >> 5, c = plane & 31;
    int grp0 = (d == 1) ? 3 : 6;

    const float* g1 = gates + ((size_t)(b * 384 + (grp0 + 0) * 32 + c)) * HW;
    const float* g2 = gates + ((size_t)(b * 384 + (grp0 + 1) * 32 + c)) * HW;
    const float* g3 = gates + ((size_t)(b * 384 + (grp0 + 2) * 32 + c)) * HW;
    const float* xp = g_x + (size_t)plane * HW;
    float* yp = g_dir + (size_t)d * NTOT + (size_t)plane * HW;

    hbuf[0][s + 1] = 0.0f;
    if (s < 2) { hbuf[0][s * 225] = 0.0f; hbuf[1][s * 225] = 0.0f; }
    __syncthreads();

    if (d == 1) scan_v_body<true>(g1, g2, g3, xp, yp, sbuf, hbuf, s);
    else        scan_v_body<false>(g1, g2, g3, xp, yp, sbuf, hbuf, s);
}

// ---------------------------------------------------------------------------
// Horizontal scan on NATIVE input layout (d0 lr = W fwd, d3 ud = W rev).
// Slab stage: 4 arrays x 224 rows x 32 cols; swizzle c^(row&7) keeps fill and
// stride-128B consume conflict-free. Output written TRANSPOSED (coalesced):
// yp[col*224 + row].
// ---------------------------------------------------------------------------
template <bool REV>
__device__ void scan_h_body(const float* __restrict__ g1,
                            const float* __restrict__ g2,
                            const float* __restrict__ g3,
                            const float* __restrict__ xp,
                            float* __restrict__ yp, char* slab,
                            float (*hbuf)[226], int s) {
    const float* arr[4] = {g1, g2, g3, xp};

    auto fill = [&](int st, int tg) {
        uint32_t sb = s2u(slab) + (uint32_t)(st * HSTAGEB);
        int base = REV ? 192 - 32 * tg : 32 * tg;
#pragma unroll
        for (int i = 0; i < 32; i++) {
            int a = i >> 3;
            int r = (i & 7) * 224 + s;
            int row = r >> 3, ch = r & 7;
            cpa16(sb + (uint32_t)(a * HARR + row * 128 +
                                  ((ch ^ (row & 7)) << 4)),
                  arr[a] + (size_t)row * WW + base + ch * 4);
        }
        cpa_commit();
    };

    fill(0, 0);
    fill(1, 1);

    int cur = 0;
    float hown = 0.0f;

    for (int tg = 0; tg < HGRP; tg++) {
        int st = tg & 1;
        cpa_wait1();
        __syncthreads();
        char* sp = slab + st * HSTAGEB;

#pragma unroll
        for (int m = 0; m < 8; m++) {
            int cm = REV ? 7 - m : m;
            float4 q[4];
#pragma unroll
            for (int a = 0; a < 4; a++)
                q[a] = *(const float4*)(sp + a * HARR + s * 128 +
                                        ((cm ^ (s & 7)) << 4));

            float a1[4], a2[4], a3[4], cx[4];
#pragma unroll
            for (int j = 0; j < 4; j++) {
                int cc = REV ? 3 - j : j;
                float G1 = ((const float*)&q[0])[cc];
                float G2 = ((const float*)&q[1])[cc];
                float G3 = ((const float*)&q[2])[cc];
                float X = ((const float*)&q[3])[cc];
                float inv = __fdividef(
                    1.0f, fmaxf(fabsf(G1) + fabsf(G2) + fabsf(G3), 1.0f));
                a1[j] = G1 * inv;
                a2[j] = G2 * inv;
                a3[j] = G3 * inv;
                cx[j] = (1.0f - a1[j] - a2[j] - a3[j]) * X;
            }

#pragma unroll
            for (int j = 0; j < 4; j++) {
                float hl = hbuf[cur][s];
                float hr = hbuf[cur][s + 2];
                float hn = fmaf(a1[j], hl,
                                fmaf(a2[j], hown, fmaf(a3[j], hr, cx[j])));
                hbuf[cur ^ 1][s + 1] = hn;
                hown = hn;
                cur ^= 1;
                __syncthreads();
                int t = 32 * tg + 4 * m + j;
                int col = REV ? 223 - t : t;
                yp[(size_t)col * 224 + s] = hn;  // transposed, coalesced
            }
        }

        if (tg + 2 < HGRP) fill(st, tg + 2);
        else cpa_commit();
    }
}

__global__ void __launch_bounds__(224) scan_h_kernel(
    const float* __restrict__ gates) {
    extern __shared__ __align__(128) char hsm[];
    float(*hbuf)[226] = (float(*)[226])(hsm + NSH * HSTAGEB);

    int s = threadIdx.x;
    int plane = blockIdx.x;
    int dh = blockIdx.y;  // 0 -> d0 (fwd), 1 -> d3 (rev)
    int b = plane >> 5, c = plane & 31;
    int grp0 = dh ? 9 : 0;

    const float* g1 = gates + ((size_t)(b * 384 + (grp0 + 0) * 32 + c)) * HW;
    const float* g2 = gates + ((size_t)(b * 384 + (grp0 + 1) * 32 + c)) * HW;
    const float* g3 = gates + ((size_t)(b * 384 + (grp0 + 2) * 32 + c)) * HW;
    const float* xp = g_x + (size_t)plane * HW;
    float* yp = g_dir + (size_t)(dh ? 3 : 0) * NTOT + (size_t)plane * HW;

    hbuf[0][s + 1] = 0.0f;
    if (s < 2) { hbuf[0][s * 225] = 0.0f; hbuf[1][s * 225] = 0.0f; }
    __syncthreads();

    if (dh) scan_h_body<true>(g1, g2, g3, xp, yp, hsm, hbuf, s);
    else    scan_h_body<false>(g1, g2, g3, xp, yp, hsm, hbuf, s);
}

// ---------------------------------------------------------------------------
// Combine: max over 4 dirs; d0,d3 transposed. Vectorized float4 version.
// Block (8,32); each thread handles 4 consecutive output columns of one row.
// Transposed tiles staged via scalar STS into [32][33] (both STS pattern
// ty+4tx+i and LDS pattern 33*(4tx+i)+ty are bank-conflict-free).
// ---------------------------------------------------------------------------
__global__ void combine_t_kernel() {
    __shared__ float t0[32][33], t3[32][33];
    int plane = blockIdx.z;
    const float* p0t = g_dir + 0 * NTOT + (size_t)plane * HW;
    const float* p1 = g_dir + 1 * NTOT + (size_t)plane * HW;
    const float* p2 = g_dir + 2 * NTOT + (size_t)plane * HW;
    const float* p3t = g_dir + 3 * NTOT + (size_t)plane * HW;
    int x0 = blockIdx.x * 32, y0 = blockIdx.y * 32;
    int tx = threadIdx.x;  // 0..7
    int ty = threadIdx.y;  // 0..31

    // Stage transposed tiles: t[r][c] = native(y0+c, x0+r), float4 loads.
    {
        float4 a0 = *(const float4*)(p0t + (size_t)(x0 + ty) * HH + y0 + 4 * tx);
        float4 a3 = *(const float4*)(p3t + (size_t)(x0 + ty) * HH + y0 + 4 * tx);
        t0[ty][4 * tx + 0] = a0.x; t0[ty][4 * tx + 1] = a0.y;
        t0[ty][4 * tx + 2] = a0.z; t0[ty][4 * tx + 3] = a0.w;
        t3[ty][4 * tx + 0] = a3.x; t3[ty][4 * tx + 1] = a3.y;
        t3[ty][4 * tx + 2] = a3.z; t3[ty][4 * tx + 3] = a3.w;
    }
    __syncthreads();

    // Combine row y0+ty, cols x0+4tx..+3.
    size_t ro = (size_t)(y0 + ty) * WW + x0 + 4 * tx;
    float4 v1 = *(const float4*)(p1 + ro);
    float4 v2 = *(const float4*)(p2 + ro);
    float4 r;
    r.x = fmaxf(fmaxf(t0[4 * tx + 0][ty], t3[4 * tx + 0][ty]),
                fmaxf(v1.x, v2.x));
    r.y = fmaxf(fmaxf(t0[4 * tx + 1][ty], t3[4 * tx + 1][ty]),
                fmaxf(v1.y, v2.y));
    r.z = fmaxf(fmaxf(t0[4 * tx + 2][ty], t3[4 * tx + 2][ty]),
                fmaxf(v1.z, v2.z));
    r.w = fmaxf(fmaxf(t0[4 * tx + 3][ty], t3[4 * tx + 3][ty]),
                fmaxf(v1.w, v2.w));
    *(float4*)(g_x + (size_t)plane * HW + ro) = r;
}

// ---------------------------------------------------------------------------
// K3: conv2d 3x3 same 32 -> 2 on g_x, fused log_softmax over the 2 channels.
// ---------------------------------------------------------------------------
__global__ void conv_out_kernel(const float* __restrict__ w4,
                                float* __restrict__ out) {
    __shared__ float ws[576];
    for (int i = threadIdx.x; i < 576; i += blockDim.x) ws[i] = w4[i];
    __syncthreads();

    int idx = blockIdx.x * blockDim.x + threadIdx.x;
    if (idx >= BB * HW) return;
    int b = idx / HW, pix = idx - b * HW;
    int py = pix / WW, px = pix - py * WW;

    float a0 = 0.0f, a1 = 0.0f;
    for (int ic = 0; ic < 32; ic++) {
        const float* ip = g_x + ((size_t)(b * 32 + ic)) * HW;
#pragma unroll
        for (int ky = 0; ky < 3; ky++) {
            int yy = py + ky - 1;
            bool vy = (unsigned)yy < HH;
#pragma unroll
            for (int kx = 0; kx < 3; kx++) {
                int xx = px + kx - 1;
                float v = (vy && (unsigned)xx < WW)
                              ? __ldg(ip + yy * WW + xx)
                              : 0.0f;
                int wi = ic * 9 + ky * 3 + kx;
                a0 += v * ws[wi];
                a1 += v * ws[288 + wi];
            }
        }
    }
    float mx = fmaxf(a0, a1);
    float l = mx + logf(expf(a0 - mx) + expf(a1 - mx));
    out[(size_t)(b * 2) * HW + pix] = a0 - l;
    out[(size_t)(b * 2 + 1) * HW + pix] = a1 - l;
}

// ---------------------------------------------------------------------------
// Launch: conv_in -> scan_v+scan_h -> combine_t -> scan_v+scan_h ->
//         combine_t -> conv_out.  (R13 structure; combine_t vectorized.)
// ---------------------------------------------------------------------------
extern "C" void kernel_launch(void* const* d_in, const int* in_sizes, int n_in,
                              void* d_out, int out_size) {
    const float* gates = (const float*)d_in[0];
    const float* y     = (const float*)d_in[1];
    const float* w3    = (const float*)d_in[2];
    const float* w4    = (const float*)d_in[3];
    float* out = (float*)d_out;

    cudaFuncSetAttribute(scan_h_kernel,
                         cudaFuncAttributeMaxDynamicSharedMemorySize, HSMEM);

    int pxblocks = (BB * HW + 255) / 256;
    dim3 sg(NPLANE, 2);
    dim3 cb(8, 32);
    dim3 cg(7, 7, NPLANE);

    conv_in_kernel<<<pxblocks, 256>>>(y, w3);
    scan_v_kernel<<<sg, 224>>>(gates);
    scan_h_kernel<<<sg, 224, HSMEM>>>(gates);
    combine_t_kernel<<<cg, cb>>>();
    scan_v_kernel<<<sg, 224>>>(gates);
    scan_h_kernel<<<sg, 224, HSMEM>>>(gates);
    combine_t_kernel<<<cg, cb>>>();
    conv_out_kernel<<<pxblocks, 256>>>(w4, out);
}

// round 17
// speedup vs baseline: 1.6922x; 1.1067x over previous
#include <cuda_runtime.h>
#include <cuda_fp16.h>
#include <cstdint>

// ---------------------------------------------------------------------------
// Problem constants
// ---------------------------------------------------------------------------
#define BB 4
#define HH 224
#define WW 224
#define HW (HH * WW)                 // 50176
#define NPLANE 128                   // B*C
#define NTOT ((size_t)NPLANE * HW)   // 6,422,528 floats

// vertical scan pipeline
#define ST 4
#define NS 3
#define NGRP (HH / ST)               // 56

// horizontal scan slab pipeline
#define STH 32                       // steps per stage (128B per row per array)
#define NSH 2
#define HGRP (WW / STH)              // 7
#define HARR (224 * STH * 4)         // bytes per array per stage = 28672
#define HSTAGEB (4 * HARR)           // 114688
#define HSMEM (NSH * HSTAGEB + 2 * 226 * 4)  // 231184

// Scratch (no cudaMalloc allowed)
__device__ __align__(256) float g_x[NTOT];
__device__ __align__(256) __half g_dir[4 * NTOT];  // fp16; d0,d3 transposed

// ---------------------------------------------------------------------------
// cp.async helpers
// ---------------------------------------------------------------------------
__device__ __forceinline__ uint32_t s2u(const void* p) {
    return (uint32_t)__cvta_generic_to_shared(p);
}
__device__ __forceinline__ void cpa16(uint32_t dst, const float* src) {
    asm volatile("cp.async.cg.shared.global [%0], [%1], 16;" ::"r"(dst),
                 "l"(src));
}
__device__ __forceinline__ void cpa16p(float* dst, const float* src) {
    cpa16(s2u(dst), src);
}
__device__ __forceinline__ void cpa_commit() {
    asm volatile("cp.async.commit_group;");
}
__device__ __forceinline__ void cpa_wait2() {
    asm volatile("cp.async.wait_group 2;");
}
__device__ __forceinline__ void cpa_wait1() {
    asm volatile("cp.async.wait_group 1;");
}

// ---------------------------------------------------------------------------
// K0: conv2d 3x3 same, 2 -> 32, writes g_x
// ---------------------------------------------------------------------------
__global__ void conv_in_kernel(const float* __restrict__ y,
                               const float* __restrict__ w3) {
    __shared__ float ws[576];
    for (int i = threadIdx.x; i < 576; i += blockDim.x) ws[i] = w3[i];
    __syncthreads();

    int idx = blockIdx.x * blockDim.x + threadIdx.x;
    if (idx >= BB * HW) return;
    int b = idx / HW, pix = idx - b * HW;
    int py = pix / WW, px = pix - py * WW;

    float in[2][3][3];
#pragma unroll
    for (int ic = 0; ic < 2; ic++)
#pragma unroll
        for (int ky = 0; ky < 3; ky++)
#pragma unroll
            for (int kx = 0; kx < 3; kx++) {
                int yy = py + ky - 1, xx = px + kx - 1;
                bool v = ((unsigned)yy < HH) && ((unsigned)xx < WW);
                in[ic][ky][kx] =
                    v ? __ldg(y + ((size_t)(b * 2 + ic)) * HW + yy * WW + xx)
                      : 0.0f;
            }

    for (int oc = 0; oc < 32; oc++) {
        float a = 0.0f;
#pragma unroll
        for (int ic = 0; ic < 2; ic++)
#pragma unroll
            for (int k = 0; k < 9; k++)
                a += in[ic][k / 3][k % 3] * ws[(oc * 2 + ic) * 9 + k];
        g_x[((size_t)(b * 32 + oc)) * HW + pix] = a;
    }
}

// ---------------------------------------------------------------------------
// Vertical scan (d1 rl = H reverse, d2 du = H forward). fp16 output.
// ---------------------------------------------------------------------------
template <bool REV>
__device__ void scan_v_body(const float* __restrict__ g1,
                            const float* __restrict__ g2,
                            const float* __restrict__ g3,
                            const float* __restrict__ xp,
                            __half* __restrict__ yp,
                            float (*sbuf)[4][ST * 224], float (*hbuf)[226],
                            int s) {
    const float* arr[4] = {g1, g2, g3, xp};
    const int jf = s / 56, qf = s - jf * 56;

    auto fill = [&](int st, int tg) {
        int row = REV ? 223 - (4 * tg + jf) : 4 * tg + jf;
#pragma unroll
        for (int a = 0; a < 4; a++)
            cpa16p(&sbuf[st][a][jf * 224 + qf * 4],
                   arr[a] + (size_t)row * WW + qf * 4);
        cpa_commit();
    };

    fill(0, 0);
    fill(1, 1);
    fill(2, 2);

    int cur = 0;
    float hown = 0.0f;

    for (int tg = 0; tg < NGRP; tg++) {
        int st = tg % NS;
        cpa_wait2();
        __syncthreads();

        float a1[ST], a2[ST], a3[ST], cx[ST];
#pragma unroll
        for (int j = 0; j < ST; j++) {
            float G1 = sbuf[st][0][j * 224 + s];
            float G2 = sbuf[st][1][j * 224 + s];
            float G3 = sbuf[st][2][j * 224 + s];
            float X = sbuf[st][3][j * 224 + s];
            float inv = __fdividef(
                1.0f, fmaxf(fabsf(G1) + fabsf(G2) + fabsf(G3), 1.0f));
            a1[j] = G1 * inv;
            a2[j] = G2 * inv;
            a3[j] = G3 * inv;
            cx[j] = (1.0f - a1[j] - a2[j] - a3[j]) * X;
        }

#pragma unroll
        for (int j = 0; j < ST; j++) {
            float hl = hbuf[cur][s];
            float hr = hbuf[cur][s + 2];
            float hn =
                fmaf(a1[j], hl, fmaf(a2[j], hown, fmaf(a3[j], hr, cx[j])));
            hbuf[cur ^ 1][s + 1] = hn;
            hown = hn;
            cur ^= 1;
            __syncthreads();
            int row = REV ? 223 - (4 * tg + j) : 4 * tg + j;
            yp[(size_t)row * WW + s] = __float2half_rn(hn);  // coalesced
        }

        int nt = tg + NS;
        if (nt < NGRP) fill(st, nt);
        else cpa_commit();
    }
}

__global__ void __launch_bounds__(224) scan_v_kernel(
    const float* __restrict__ gates) {
    __shared__ float sbuf[NS][4][ST * 224];
    __shared__ float hbuf[2][226];

    int s = threadIdx.x;
    int plane = blockIdx.x;
    int d = blockIdx.y + 1;  // 1 or 2
    int b = plane >> 5, c = plane & 31;
    int grp0 = (d == 1) ? 3 : 6;

    const float* g1 = gates + ((size_t)(b * 384 + (grp0 + 0) * 32 + c)) * HW;
    const float* g2 = gates + ((size_t)(b * 384 + (grp0 + 1) * 32 + c)) * HW;
    const float* g3 = gates + ((size_t)(b * 384 + (grp0 + 2) * 32 + c)) * HW;
    const float* xp = g_x + (size_t)plane * HW;
    __half* yp = g_dir + (size_t)d * NTOT + (size_t)plane * HW;

    hbuf[0][s + 1] = 0.0f;
    if (s < 2) { hbuf[0][s * 225] = 0.0f; hbuf[1][s * 225] = 0.0f; }
    __syncthreads();

    if (d == 1) scan_v_body<true>(g1, g2, g3, xp, yp, sbuf, hbuf, s);
    else        scan_v_body<false>(g1, g2, g3, xp, yp, sbuf, hbuf, s);
}

// ---------------------------------------------------------------------------
// Horizontal scan on NATIVE input layout (d0 lr = W fwd, d3 ud = W rev).
// Slab stage: 4 arrays x 224 rows x 32 cols; swizzle c^(row&7) keeps fill and
// stride-128B consume conflict-free. Output TRANSPOSED fp16 (coalesced):
// yp[col*224 + row].
// ---------------------------------------------------------------------------
template <bool REV>
__device__ void scan_h_body(const float* __restrict__ g1,
                            const float* __restrict__ g2,
                            const float* __restrict__ g3,
                            const float* __restrict__ xp,
                            __half* __restrict__ yp, char* slab,
                            float (*hbuf)[226], int s) {
    const float* arr[4] = {g1, g2, g3, xp};

    auto fill = [&](int st, int tg) {
        uint32_t sb = s2u(slab) + (uint32_t)(st * HSTAGEB);
        int base = REV ? 192 - 32 * tg : 32 * tg;
#pragma unroll
        for (int i = 0; i < 32; i++) {
            int a = i >> 3;
            int r = (i & 7) * 224 + s;
            int row = r >> 3, ch = r & 7;
            cpa16(sb + (uint32_t)(a * HARR + row * 128 +
                                  ((ch ^ (row & 7)) << 4)),
                  arr[a] + (size_t)row * WW + base + ch * 4);
        }
        cpa_commit();
    };

    fill(0, 0);
    fill(1, 1);

    int cur = 0;
    float hown = 0.0f;

    for (int tg = 0; tg < HGRP; tg++) {
        int st = tg & 1;
        cpa_wait1();
        __syncthreads();
        char* sp = slab + st * HSTAGEB;

#pragma unroll
        for (int m = 0; m < 8; m++) {
            int cm = REV ? 7 - m : m;
            float4 q[4];
#pragma unroll
            for (int a = 0; a < 4; a++)
                q[a] = *(const float4*)(sp + a * HARR + s * 128 +
                                        ((cm ^ (s & 7)) << 4));

            float a1[4], a2[4], a3[4], cx[4];
#pragma unroll
            for (int j = 0; j < 4; j++) {
                int cc = REV ? 3 - j : j;
                float G1 = ((const float*)&q[0])[cc];
                float G2 = ((const float*)&q[1])[cc];
                float G3 = ((const float*)&q[2])[cc];
                float X = ((const float*)&q[3])[cc];
                float inv = __fdividef(
                    1.0f, fmaxf(fabsf(G1) + fabsf(G2) + fabsf(G3), 1.0f));
                a1[j] = G1 * inv;
                a2[j] = G2 * inv;
                a3[j] = G3 * inv;
                cx[j] = (1.0f - a1[j] - a2[j] - a3[j]) * X;
            }

#pragma unroll
            for (int j = 0; j < 4; j++) {
                float hl = hbuf[cur][s];
                float hr = hbuf[cur][s + 2];
                float hn = fmaf(a1[j], hl,
                                fmaf(a2[j], hown, fmaf(a3[j], hr, cx[j])));
                hbuf[cur ^ 1][s + 1] = hn;
                hown = hn;
                cur ^= 1;
                __syncthreads();
                int t = 32 * tg + 4 * m + j;
                int col = REV ? 223 - t : t;
                yp[(size_t)col * 224 + s] = __float2half_rn(hn);
            }
        }

        if (tg + 2 < HGRP) fill(st, tg + 2);
        else cpa_commit();
    }
}

__global__ void __launch_bounds__(224) scan_h_kernel(
    const float* __restrict__ gates) {
    extern __shared__ __align__(128) char hsm[];
    float(*hbuf)[226] = (float(*)[226])(hsm + NSH * HSTAGEB);

    int s = threadIdx.x;
    int plane = blockIdx.x;
    int dh = blockIdx.y;  // 0 -> d0 (fwd), 1 -> d3 (rev)
    int b = plane >> 5, c = plane & 31;
    int grp0 = dh ? 9 : 0;

    const float* g1 = gates + ((size_t)(b * 384 + (grp0 + 0) * 32 + c)) * HW;
    const float* g2 = gates + ((size_t)(b * 384 + (grp0 + 1) * 32 + c)) * HW;
    const float* g3 = gates + ((size_t)(b * 384 + (grp0 + 2) * 32 + c)) * HW;
    const float* xp = g_x + (size_t)plane * HW;
    __half* yp = g_dir + (size_t)(dh ? 3 : 0) * NTOT + (size_t)plane * HW;

    hbuf[0][s + 1] = 0.0f;
    if (s < 2) { hbuf[0][s * 225] = 0.0f; hbuf[1][s * 225] = 0.0f; }
    __syncthreads();

    if (dh) scan_h_body<true>(g1, g2, g3, xp, yp, hsm, hbuf, s);
    else    scan_h_body<false>(g1, g2, g3, xp, yp, hsm, hbuf, s);
}

// ---------------------------------------------------------------------------
// Combine: max over 4 dirs (fp16 in, fp32 out); d0,d3 transposed.
// Block (8,32); each thread: 4 consecutive output columns of one row.
// Transposed tiles staged as floats in [32][33] (conflict-free patterns).
// ---------------------------------------------------------------------------
__global__ void combine_t_kernel() {
    __shared__ float t0[32][33], t3[32][33];
    int plane = blockIdx.z;
    const __half* p0t = g_dir + 0 * NTOT + (size_t)plane * HW;
    const __half* p1 = g_dir + 1 * NTOT + (size_t)plane * HW;
    const __half* p2 = g_dir + 2 * NTOT + (size_t)plane * HW;
    const __half* p3t = g_dir + 3 * NTOT + (size_t)plane * HW;
    int x0 = blockIdx.x * 32, y0 = blockIdx.y * 32;
    int tx = threadIdx.x;  // 0..7
    int ty = threadIdx.y;  // 0..31

    // Stage transposed tiles: t[r][c] = native(y0+c, x0+r); 4 halves/thread.
    {
        size_t to = (size_t)(x0 + ty) * HH + y0 + 4 * tx;
        uint2 u0 = *(const uint2*)(p0t + to);
        uint2 u3 = *(const uint2*)(p3t + to);
        float2 a0 = __half22float2(*(const __half2*)&u0.x);
        float2 b0 = __half22float2(*(const __half2*)&u0.y);
        float2 a3 = __half22float2(*(const __half2*)&u3.x);
        float2 b3 = __half22float2(*(const __half2*)&u3.y);
        t0[ty][4 * tx + 0] = a0.x; t0[ty][4 * tx + 1] = a0.y;
        t0[ty][4 * tx + 2] = b0.x; t0[ty][4 * tx + 3] = b0.y;
        t3[ty][4 * tx + 0] = a3.x; t3[ty][4 * tx + 1] = a3.y;
        t3[ty][4 * tx + 2] = b3.x; t3[ty][4 * tx + 3] = b3.y;
    }
    __syncthreads();

    // Combine row y0+ty, cols x0+4tx..+3.
    size_t ro = (size_t)(y0 + ty) * WW + x0 + 4 * tx;
    uint2 u1 = *(const uint2*)(p1 + ro);
    uint2 u2 = *(const uint2*)(p2 + ro);
    float2 f1a = __half22float2(*(const __half2*)&u1.x);
    float2 f1b = __half22float2(*(const __half2*)&u1.y);
    float2 f2a = __half22float2(*(const __half2*)&u2.x);
    float2 f2b = __half22float2(*(const __half2*)&u2.y);
    float4 r;
    r.x = fmaxf(fmaxf(t0[4 * tx + 0][ty], t3[4 * tx + 0][ty]),
                fmaxf(f1a.x, f2a.x));
    r.y = fmaxf(fmaxf(t0[4 * tx + 1][ty], t3[4 * tx + 1][ty]),
                fmaxf(f1a.y, f2a.y));
    r.z = fmaxf(fmaxf(t0[4 * tx + 2][ty], t3[4 * tx + 2][ty]),
                fmaxf(f1b.x, f2b.x));
    r.w = fmaxf(fmaxf(t0[4 * tx + 3][ty], t3[4 * tx + 3][ty]),
                fmaxf(f1b.y, f2b.y));
    *(float4*)(g_x + (size_t)plane * HW + ro) = r;
}

// ---------------------------------------------------------------------------
// K3: conv2d 3x3 same 32 -> 2 on g_x, fused log_softmax over the 2 channels.
// ---------------------------------------------------------------------------
__global__ void conv_out_kernel(const float* __restrict__ w4,
                                float* __restrict__ out) {
    __shared__ float ws[576];
    for (int i = threadIdx.x; i < 576; i += blockDim.x) ws[i] = w4[i];
    __syncthreads();

    int idx = blockIdx.x * blockDim.x + threadIdx.x;
    if (idx >= BB * HW) return;
    int b = idx / HW, pix = idx - b * HW;
    int py = pix / WW, px = pix - py * WW;

    float a0 = 0.0f, a1 = 0.0f;
    for (int ic = 0; ic < 32; ic++) {
        const float* ip = g_x + ((size_t)(b * 32 + ic)) * HW;
#pragma unroll
        for (int ky = 0; ky < 3; ky++) {
            int yy = py + ky - 1;
            bool vy = (unsigned)yy < HH;
#pragma unroll
            for (int kx = 0; kx < 3; kx++) {
                int xx = px + kx - 1;
                float v = (vy && (unsigned)xx < WW)
                              ? __ldg(ip + yy * WW + xx)
                              : 0.0f;
                int wi = ic * 9 + ky * 3 + kx;
                a0 += v * ws[wi];
                a1 += v * ws[288 + wi];
            }
        }
    }
    float mx = fmaxf(a0, a1);
    float l = mx + logf(expf(a0 - mx) + expf(a1 - mx));
    out[(size_t)(b * 2) * HW + pix] = a0 - l;
    out[(size_t)(b * 2 + 1) * HW + pix] = a1 - l;
}

// ---------------------------------------------------------------------------
// Launch: conv_in -> scan_v+scan_h -> combine_t -> scan_v+scan_h ->
//         combine_t -> conv_out.  (R16 structure; g_dir in fp16.)
// ---------------------------------------------------------------------------
extern "C" void kernel_launch(void* const* d_in, const int* in_sizes, int n_in,
                              void* d_out, int out_size) {
    const float* gates = (const float*)d_in[0];
    const float* y     = (const float*)d_in[1];
    const float* w3    = (const float*)d_in[2];
    const float* w4    = (const float*)d_in[3];
    float* out = (float*)d_out;

    cudaFuncSetAttribute(scan_h_kernel,
                         cudaFuncAttributeMaxDynamicSharedMemorySize, HSMEM);

    int pxblocks = (BB * HW + 255) / 256;
    dim3 sg(NPLANE, 2);
    dim3 cb(8, 32);
    dim3 cg(7, 7, NPLANE);

    conv_in_kernel<<<pxblocks, 256>>>(y, w3);
    scan_v_kernel<<<sg, 224>>>(gates);
    scan_h_kernel<<<sg, 224, HSMEM>>>(gates);
    combine_t_kernel<<<cg, cb>>>();
    scan_v_kernel<<<sg, 224>>>(gates);
    scan_h_kernel<<<sg, 224, HSMEM>>>(gates);
    combine_t_kernel<<<cg, cb>>>();
    conv_out_kernel<<<pxblocks, 256>>>(w4, out);
}